// round 5
// baseline (speedup 1.0000x reference)
#include <cuda_runtime.h>
#include <math.h>

#define BB 8
#define NN 8192
#define HH 32
#define WW 32
#define DD 256
#define HW (HH * WW)                 // 1024
#define ZQ_SIZE (BB * DD * HH * WW)  // 2097152
#define NPOS (BB * HH * WW)          // 8192
#define NBLK3 1024                   // (b,h,w-quarter)
#define KLW 5e-4f
#define LOG_N 9.010913347279288f     // log(8192)

__device__ float        g_kl_partial[NBLK3];
__device__ unsigned int g_arrive = 0;          // self-resetting; replay-safe

__global__ void __launch_bounds__(128, 8)
gumbel_fused_kernel(const float* __restrict__ z,
                    const float* __restrict__ Wt,
                    const float* __restrict__ g,
                    float* __restrict__ out)
{
    const int bidx = blockIdx.x;     // 0..1023
    const int bh   = bidx >> 2;      // (b,h)
    const int q    = bidx & 3;       // w-quarter: w in [q*8, q*8+8)
    const int b    = bh >> 5;
    const int h    = bh & 31;
    const int tid  = threadIdx.x;    // 0..127
    const int grp  = tid & 1;        // w-quad within quarter: local w = grp*4..+3
    const int np   = tid >> 1;       // n-partition 0..63

    // smem union: stats (8KB, phase 1-2) overlaid with gather rows (phase 3-4)
    __shared__ __align__(16) unsigned char s_buf[8 * 257 * 4];   // 8224B
    float (*s_m1)[8] = (float (*)[8])(s_buf);            // 2KB
    int   (*s_a1)[8] = (int   (*)[8])(s_buf + 2048);     // 2KB
    float (*s_S )[8] = (float (*)[8])(s_buf + 4096);     // 2KB
    float (*s_T )[8] = (float (*)[8])(s_buf + 6144);     // 2KB
    float (*s_rows)[DD + 1] = (float (*)[DD + 1])(s_buf);// 8.2KB (reuse)
    __shared__ int   s_ind[8];
    __shared__ bool  s_last;

    // element base: (b, n=np, h, w = q*8 + grp*4)
    const long long base =
        (long long)(b * NN + np) * HW + h * WW + q * 8 + grp * 4;
    const float4* zp = (const float4*)(z + base);
    const float4* gp = (const float4*)(g + base);
    const int strideV = 64 * HW / 4;          // float4 units per iteration

    float m1x=-INFINITY, m1y=-INFINITY, m1z=-INFINITY, m1w=-INFINITY;
    int   a1x=0, a1y=0, a1z=0, a1w=0;
    float Sx=0.f, Sy=0.f, Sz=0.f, Sw=0.f;
    float Tx=0.f, Ty=0.f, Tz=0.f, Tw=0.f;

    #pragma unroll 4
    for (int i = 0; i < 128; ++i) {
        const int n = np + i * 64;
        const float4 zv = __ldg(zp + (long long)i * strideV);
        const float4 gv = __ldg(gp + (long long)i * strideV);

        // argmax of z+g (strict > keeps first index, like jnp.argmax)
        float lg;
        lg = zv.x + gv.x; if (lg > m1x) { m1x = lg; a1x = n; }
        lg = zv.y + gv.y; if (lg > m1y) { m1y = lg; a1y = n; }
        lg = zv.z + gv.z; if (lg > m1z) { m1z = lg; a1z = n; }
        lg = zv.w + gv.w; if (lg > m1w) { m1w = lg; a1w = n; }

        // shift-free softmax stats: z ~ N(0,1) -> exp safe in fp32
        float e;
        e = __expf(zv.x); Sx += e; Tx = fmaf(e, zv.x, Tx);
        e = __expf(zv.y); Sy += e; Ty = fmaf(e, zv.y, Ty);
        e = __expf(zv.z); Sz += e; Tz = fmaf(e, zv.z, Tz);
        e = __expf(zv.w); Sw += e; Tw = fmaf(e, zv.w, Tw);
    }

    const int w0 = grp * 4;
    s_m1[np][w0+0]=m1x; s_m1[np][w0+1]=m1y; s_m1[np][w0+2]=m1z; s_m1[np][w0+3]=m1w;
    s_a1[np][w0+0]=a1x; s_a1[np][w0+1]=a1y; s_a1[np][w0+2]=a1z; s_a1[np][w0+3]=a1w;
    s_S [np][w0+0]=Sx;  s_S [np][w0+1]=Sy;  s_S [np][w0+2]=Sz;  s_S [np][w0+3]=Sw;
    s_T [np][w0+0]=Tx;  s_T [np][w0+1]=Ty;  s_T [np][w0+2]=Tz;  s_T [np][w0+3]=Tw;
    __syncthreads();

    if (tid < 8) {
        const int wl = tid;          // local w position 0..7
        float M1 = s_m1[0][wl]; int A1 = s_a1[0][wl];
        float S = s_S[0][wl];  float T = s_T[0][wl];
        #pragma unroll
        for (int i = 1; i < 64; ++i) {
            const float v = s_m1[i][wl]; const int a = s_a1[i][wl];
            if (v > M1 || (v == M1 && a < A1)) { M1 = v; A1 = a; }
            S += s_S[i][wl];
            T += s_T[i][wl];
        }
        float kl = T / S - __logf(S) + LOG_N;

        s_ind[wl] = A1;
        out[ZQ_SIZE + 1 + bh * 32 + q * 8 + wl] = (float)A1;

        #pragma unroll
        for (int off = 4; off; off >>= 1)
            kl += __shfl_xor_sync(0x000000ffu, kl, off, 8);
        if (wl == 0) g_kl_partial[bidx] = kl;
    }
    __syncthreads();   // combine done reading stats -> safe to overwrite with rows

    // z_q gather: stage 8 embedding rows coalesced (overlaying stats smem)
    #pragma unroll
    for (int r = 0; r < 8; ++r) {
        const int row = s_ind[r];
        s_rows[r][tid]       = __ldg(Wt + row * DD + tid);
        s_rows[r][tid + 128] = __ldg(Wt + row * DD + tid + 128);
    }
    __syncthreads();

    // transposed write: out[((b*256+d)*1024) + h*32 + w], w = q*8 + wl
    const int wl = tid & 7;
    const int wn = tid >> 3;         // 0..15, each covers 16 d values
    const int obase = (b * DD) * HW + h * WW + q * 8 + wl;
    #pragma unroll 8
    for (int k = 0; k < 16; ++k) {
        const int d = wn * 16 + k;
        out[obase + d * HW] = s_rows[wl][d];
    }

    // ---- last-CTA finalize (single-launch graph) ----
    if (tid == 0) {
        __threadfence();
        const unsigned old = atomicAdd(&g_arrive, 1u);
        s_last = (old == NBLK3 - 1);
    }
    __syncthreads();
    if (s_last) {
        float v = 0.f;
        #pragma unroll
        for (int j = 0; j < 8; ++j)
            v += g_kl_partial[tid + j * 128];
        #pragma unroll
        for (int off = 16; off; off >>= 1)
            v += __shfl_xor_sync(0xffffffffu, v, off);
        __shared__ float s_red[4];
        if ((tid & 31) == 0) s_red[tid >> 5] = v;
        __syncthreads();
        if (tid < 4) {
            float x = s_red[tid];
            #pragma unroll
            for (int off = 2; off; off >>= 1)
                x += __shfl_xor_sync(0x0000000fu, x, off, 4);
            if (tid == 0) {
                out[ZQ_SIZE] = KLW * (x / (float)NPOS);
                g_arrive = 0;                        // reset for next replay
            }
        }
    }
}

extern "C" void kernel_launch(void* const* d_in, const int* in_sizes, int n_in,
                              void* d_out, int out_size)
{
    const float* z  = (const float*)d_in[0];
    const float* Wt = (const float*)d_in[1];
    const float* g  = (const float*)d_in[2];
    float* out = (float*)d_out;

    gumbel_fused_kernel<<<NBLK3, 128>>>(z, Wt, g, out);
}